// round 5
// baseline (speedup 1.0000x reference)
#include <cuda_runtime.h>

#define N_NODES 200000
#define HIDDIM  256
#define HEADS   8
#define HD      32
#define NC      1000
#define TR      32     // rows per tile in k_main
#define NB      200    // hist/scatter blocks
#define CHUNK   (N_NODES / NB)   // 1000, exact
#define SPLIT   4      // parts per cluster in k_main

// ---------------- device scratch ----------------
__device__ float g_QK[HIDDIM * HEADS];       // [hpair][j] float2 pairs, scale folded in
__device__ float g_bq[HEADS];
__device__ int   g_bh[NB * NC];              // per-block cluster histograms -> bases
__device__ int   g_offsets[NC + 1];
__device__ int   g_sorted[N_NODES];
__device__ float g_T[SPLIT * NC * HEADS * HIDDIM];  // per part partial sums
__device__ float g_z[SPLIT * NC * HEADS];

// ---------------- helpers ----------------
__device__ __forceinline__ unsigned su32(const void* p) {
    return (unsigned)__cvta_generic_to_shared(p);
}
__device__ __forceinline__ void cpa16(void* dst, const void* src) {
    asm volatile("cp.async.cg.shared.global [%0], [%1], 16;"
                 :: "r"(su32(dst)), "l"(src));
}
__device__ __forceinline__ void cpa_commit() {
    asm volatile("cp.async.commit_group;");
}
template <int NN> __device__ __forceinline__ void cpa_wait() {
    asm volatile("cp.async.wait_group %0;" :: "n"(NN));
}
__device__ __forceinline__ float2 ffma2(float2 a, float2 b, float2 c) {
    float2 d;
    asm("{\n\t"
        ".reg .b64 A,B,C,D;\n\t"
        "mov.b64 A,{%2,%3};\n\t"
        "mov.b64 B,{%4,%5};\n\t"
        "mov.b64 C,{%6,%7};\n\t"
        "fma.rn.f32x2 D,A,B,C;\n\t"
        "mov.b64 {%0,%1},D;\n\t"
        "}"
        : "=f"(d.x), "=f"(d.y)
        : "f"(a.x), "f"(a.y), "f"(b.x), "f"(b.y), "f"(c.x), "f"(c.y));
    return d;
}

// ---------------- prep (blocks 0..7) + per-block histogram (blocks 8..8+NB-1) -------
__global__ void k_prep_hist(const float* __restrict__ Wk, const float* __restrict__ bk,
                            const float* __restrict__ pq, const int* __restrict__ ca) {
    __shared__ int sh[NC];
    int tid = threadIdx.x;
    if (blockIdx.x < 8) {
        const float scale = 0.1767766952966369f;  // 32^-0.5
        int h = blockIdx.x;
        int j = tid;
        float s = 0.f;
        #pragma unroll 8
        for (int d = 0; d < HD; d++)
            s += Wk[(h * HD + d) * HIDDIM + j] * pq[h * HD + d];
        g_QK[(((h >> 1) * HIDDIM) + j) * 2 + (h & 1)] = s * scale;
        if (j == 0) {
            float b = 0.f;
            for (int d = 0; d < HD; d++) b += bk[h * HD + d] * pq[h * HD + d];
            g_bq[h] = b * scale;
        }
        return;
    }
    int b = blockIdx.x - 8;
    for (int i = tid; i < NC; i += 256) sh[i] = 0;
    __syncthreads();
    int n0 = b * CHUNK;
    for (int i = tid; i < CHUNK; i += 256)
        atomicAdd(&sh[ca[n0 + i]], 1);
    __syncthreads();
    for (int i = tid; i < NC; i += 256) g_bh[b * NC + i] = sh[i];
}

// ---------------- scan: cluster offsets + per-block bases ----------------
__global__ void k_scan2() {
    __shared__ int buf[1024];
    int t = threadIdx.x;
    int total = 0;
    if (t < NC) {
        int s = 0;
        for (int b = 0; b < NB; b++) {
            int v = g_bh[b * NC + t];
            g_bh[b * NC + t] = s;
            s += v;
        }
        total = s;
    }
    buf[t] = total;
    __syncthreads();
    for (int off = 1; off < 1024; off <<= 1) {
        int add = (t >= off) ? buf[t - off] : 0;
        __syncthreads();
        buf[t] += add;
        __syncthreads();
    }
    if (t < NC) {
        int excl = buf[t] - total;
        g_offsets[t] = excl;
        for (int b = 0; b < NB; b++) g_bh[b * NC + t] += excl;
    }
    if (t == 0) g_offsets[NC] = N_NODES;
}

// ---------------- scatter (shared-memory cursors only) ----------------
__global__ void k_scatter2(const int* __restrict__ ca) {
    __shared__ int cur[NC];
    int b = blockIdx.x, tid = threadIdx.x;
    for (int i = tid; i < NC; i += 256) cur[i] = g_bh[b * NC + i];
    __syncthreads();
    int n0 = b * CHUNK;
    for (int i = tid; i < CHUNK; i += 256) {
        int n = n0 + i;
        int c = ca[n];
        int p = atomicAdd(&cur[c], 1);
        g_sorted[p] = n;
    }
}

// ---------------- main (fused scores + exp + weighted accum, quarter-clusters) ------
// dyn smem (bytes): xs 2*TR*256*4=65536 | QKs 8192 | es 1024 | zsh 256 | bqs 64
#define SM_XS   0
#define SM_QK   65536
#define SM_ES   (SM_QK + 8192)
#define SM_ZSH  (SM_ES + 1024)
#define SM_BQ   (SM_ZSH + 256)
#define SMEM_MAIN (SM_BQ + 64)

__global__ void __launch_bounds__(256) k_main(const float* __restrict__ x) {
    extern __shared__ char smem[];
    float*  xs  = (float*)(smem + SM_XS);          // [2][TR][256]
    float2* QKs = (float2*)(smem + SM_QK);         // [4][256]  (head-pairs)
    float*  esf = (float*)(smem + SM_ES);          // [TR][8]
    float*  zsh = (float*)(smem + SM_ZSH);         // [8][8]
    float*  bqs = (float*)(smem + SM_BQ);

    int tid = threadIdx.x;
    int warp = tid >> 5, lane = tid & 31;

    int cidx = blockIdx.x >> 2, part = blockIdx.x & 3;
    int cbase = g_offsets[cidx];
    int ccnt  = g_offsets[cidx + 1] - cbase;
    int ql    = (ccnt + 3) >> 2;
    int start = part * ql;
    int cnt   = min(ql, ccnt - start);
    if (cnt < 0) cnt = 0;
    int base  = cbase + start;
    int ntiles = (cnt + TR - 1) / TR;

    for (int i = tid; i < HIDDIM * 4; i += 256)
        QKs[i] = ((const float2*)g_QK)[i];
    if (tid < 8) bqs[tid] = g_bq[tid];
    __syncthreads();

    float2 T01 = make_float2(0.f, 0.f), T23 = T01, T45 = T01, T67 = T01;
    int g8 = lane >> 3;           // head group 0..3
    float zacc1 = 0.f, zacc2 = 0.f;  // heads g8 and g8+4, valid at (lane&7)==0

    int my_r = tid >> 3;
    int my_q = tid & 7;

    if (ntiles > 0) {
        int m0 = min(TR, cnt);
        if (my_r < m0) {
            int row = __ldg(&g_sorted[base + my_r]);
            const float4* src = ((const float4*)x) + (size_t)row * 64 + my_q;
            float4* dst = ((float4*)(xs + (size_t)my_r * HIDDIM)) + my_q;
            #pragma unroll
            for (int kk = 0; kk < 8; kk++)
                cpa16(dst + 8 * kk, src + 8 * kk);
        }
    }
    cpa_commit();

    for (int t = 0; t < ntiles; t++) {
        int b = t & 1;
        int m = min(TR, cnt - t * TR);
        float* xsb = xs + (size_t)b * TR * HIDDIM;

        if (t + 1 < ntiles) {
            int m2 = min(TR, cnt - (t + 1) * TR);
            float* xsn = xs + (size_t)(b ^ 1) * TR * HIDDIM;
            if (my_r < m2) {
                int row = __ldg(&g_sorted[base + (t + 1) * TR + my_r]);
                const float4* src = ((const float4*)x) + (size_t)row * 64 + my_q;
                float4* dst = ((float4*)(xsn + (size_t)my_r * HIDDIM)) + my_q;
                #pragma unroll
                for (int kk = 0; kk < 8; kk++)
                    cpa16(dst + 8 * kk, src + 8 * kk);
            }
            cpa_commit();
            cpa_wait<1>();
        } else {
            cpa_wait<0>();
        }
        __syncthreads();

        // ---- scores: warp handles rows 4*warp .. 4*warp+3 ----
        {
            float2 s[4][4];
            #pragma unroll
            for (int rr = 0; rr < 4; rr++)
                #pragma unroll
                for (int p = 0; p < 4; p++) s[rr][p] = make_float2(0.f, 0.f);

            #pragma unroll
            for (int k = 0; k < 8; k++) {
                int j = lane + 32 * k;
                float2 q0 = QKs[0 * HIDDIM + j];
                float2 q1 = QKs[1 * HIDDIM + j];
                float2 q2 = QKs[2 * HIDDIM + j];
                float2 q3 = QKs[3 * HIDDIM + j];
                #pragma unroll
                for (int rr = 0; rr < 4; rr++) {
                    float xv = xsb[(warp * 4 + rr) * HIDDIM + j];
                    float2 xx = make_float2(xv, xv);
                    s[rr][0] = ffma2(xx, q0, s[rr][0]);
                    s[rr][1] = ffma2(xx, q1, s[rr][1]);
                    s[rr][2] = ffma2(xx, q2, s[rr][2]);
                    s[rr][3] = ffma2(xx, q3, s[rr][3]);
                }
            }
            #pragma unroll
            for (int rr = 0; rr < 4; rr++) {
                int r = warp * 4 + rr;
                float v[8] = {s[rr][0].x, s[rr][0].y, s[rr][1].x, s[rr][1].y,
                              s[rr][2].x, s[rr][2].y, s[rr][3].x, s[rr][3].y};
                // stage 1: reduce over lane classes mod 8 (2 butterfly steps)
                #pragma unroll
                for (int h = 0; h < 8; h++) {
                    v[h] += __shfl_xor_sync(0xffffffffu, v[h], 16);
                    v[h] += __shfl_xor_sync(0xffffffffu, v[h], 8);
                }
                // stage 2: lane keeps heads g8 and g8+4; reduce over the 8 classes
                float w1 = (g8 == 0) ? v[0] : (g8 == 1) ? v[1] : (g8 == 2) ? v[2] : v[3];
                float w2 = (g8 == 0) ? v[4] : (g8 == 1) ? v[5] : (g8 == 2) ? v[6] : v[7];
                w1 += __shfl_xor_sync(0xffffffffu, w1, 1);
                w1 += __shfl_xor_sync(0xffffffffu, w1, 2);
                w1 += __shfl_xor_sync(0xffffffffu, w1, 4);
                w2 += __shfl_xor_sync(0xffffffffu, w2, 1);
                w2 += __shfl_xor_sync(0xffffffffu, w2, 2);
                w2 += __shfl_xor_sync(0xffffffffu, w2, 4);
                if ((lane & 7) == 0 && r < m) {
                    float e1 = __expf(w1 + bqs[g8]);
                    float e2 = __expf(w2 + bqs[g8 + 4]);
                    esf[r * 8 + g8]     = e1;
                    esf[r * 8 + g8 + 4] = e2;
                    zacc1 += e1;
                    zacc2 += e2;
                }
            }
        }
        __syncthreads();

        // ---- accumulate T: thread owns column j = tid ----
        for (int r = 0; r < m; r++) {
            float xv = xsb[r * HIDDIM + tid];
            float2 xx = make_float2(xv, xv);
            float4 ea = ((const float4*)(esf + r * 8))[0];
            float4 eb = ((const float4*)(esf + r * 8))[1];
            T01 = ffma2(make_float2(ea.x, ea.y), xx, T01);
            T23 = ffma2(make_float2(ea.z, ea.w), xx, T23);
            T45 = ffma2(make_float2(eb.x, eb.y), xx, T45);
            T67 = ffma2(make_float2(eb.z, eb.w), xx, T67);
        }
        __syncthreads();
    }

    float* Tp = g_T + (size_t)blockIdx.x * 8 * HIDDIM;
    Tp[0 * HIDDIM + tid] = T01.x;
    Tp[1 * HIDDIM + tid] = T01.y;
    Tp[2 * HIDDIM + tid] = T23.x;
    Tp[3 * HIDDIM + tid] = T23.y;
    Tp[4 * HIDDIM + tid] = T45.x;
    Tp[5 * HIDDIM + tid] = T45.y;
    Tp[6 * HIDDIM + tid] = T67.x;
    Tp[7 * HIDDIM + tid] = T67.y;

    if ((lane & 7) == 0) {
        zsh[warp * 8 + g8]     = zacc1;
        zsh[warp * 8 + g8 + 4] = zacc2;
    }
    __syncthreads();
    if (tid < 8) {
        float z = 0.f;
        #pragma unroll
        for (int w = 0; w < 8; w++) z += zsh[w * 8 + tid];
        g_z[blockIdx.x * 8 + tid] = z;
    }
}

// ---------------- fused: pooled (Wv) -> outc (Wo) -> scatter output ----------------
__global__ void __launch_bounds__(256) k_fused(
    const float* __restrict__ Wv, const float* __restrict__ bv,
    const float* __restrict__ Wo, const float* __restrict__ bo,
    float* __restrict__ out) {
    __shared__ float Ws[256 * 33];
    __shared__ float TsPp[2112];     // Ts[8][8][33] in phase1, Pp/out rows [8][256] later
    __shared__ float sinvz[64];
    __shared__ float sinvc[8];
    __shared__ int   sids[256];

    int tid = threadIdx.x;
    int c0 = blockIdx.x * 8;
    int h = tid >> 5;

    if (tid < 64) {
        int cc = tid >> 3, hh = tid & 7;
        float z = 0.f;
        #pragma unroll
        for (int p = 0; p < SPLIT; p++)
            z += g_z[(c0 + cc) * (8 * SPLIT) + p * 8 + hh];
        sinvz[tid] = (z > 0.f) ? 1.f / z : 0.f;
    }
    if (tid < 8) {
        int cnt = g_offsets[c0 + tid + 1] - g_offsets[c0 + tid];
        sinvc[tid] = (cnt > 0) ? 1.f / (float)cnt : 0.f;
    }

    // ---- phase 1: pooled[c][hd] = (sum_j T'[c,h,j] Wv[hd,j] + bv[hd]) / cnt ----
    float acc[8];
    #pragma unroll
    for (int cc = 0; cc < 8; cc++) acc[cc] = 0.f;

    for (int kt = 0; kt < HIDDIM; kt += 32) {
        __syncthreads();
        for (int i = tid; i < 8192; i += 256) {
            int hd = i >> 5, kk = i & 31;
            Ws[hd * 33 + kk] = Wv[hd * HIDDIM + kt + kk];
        }
        for (int i = tid; i < 2048; i += 256) {
            int cc = i >> 8, hh = (i >> 5) & 7, kk = i & 31;
            size_t b0 = ((size_t)(c0 + cc) * SPLIT) * 2048 + hh * 256 + kt + kk;
            float tv = 0.f;
            #pragma unroll
            for (int p = 0; p < SPLIT; p++) tv += g_T[b0 + (size_t)p * 2048];
            TsPp[(cc * 8 + hh) * 33 + kk] = tv * sinvz[cc * 8 + hh];
        }
        __syncthreads();
        for (int kk = 0; kk < 32; kk++) {
            float w = Ws[tid * 33 + kk];
            #pragma unroll
            for (int cc = 0; cc < 8; cc++) acc[cc] += TsPp[(cc * 8 + h) * 33 + kk] * w;
        }
    }
    __syncthreads();
    {
        float bvv = bv[tid];
        #pragma unroll
        for (int cc = 0; cc < 8; cc++)
            TsPp[cc * 256 + tid] = (acc[cc] + bvv) * sinvc[cc];  // Pp[cc][hd]
    }
    __syncthreads();

    // ---- phase 2: outc[c][d] = sum_k pooled[c][k] * Wo[d][k] + bo[d] ----
    float acc2[8];
    #pragma unroll
    for (int cc = 0; cc < 8; cc++) acc2[cc] = 0.f;

    for (int kt = 0; kt < HIDDIM; kt += 32) {
        __syncthreads();
        for (int i = tid; i < 8192; i += 256) {
            int hd = i >> 5, kk = i & 31;
            Ws[hd * 33 + kk] = Wo[hd * HIDDIM + kt + kk];
        }
        __syncthreads();
        for (int kk = 0; kk < 32; kk++) {
            float w = Ws[tid * 33 + kk];
            #pragma unroll
            for (int cc = 0; cc < 8; cc++) acc2[cc] += TsPp[cc * 256 + kt + kk] * w;
        }
    }
    __syncthreads();
    {
        float bov = bo[tid];
        #pragma unroll
        for (int cc = 0; cc < 8; cc++)
            TsPp[cc * 256 + tid] = acc2[cc] + bov;   // out rows
    }
    __syncthreads();

    // ---- phase 3: out[n,:] = outrow[cc] for every member n of cluster ----
    int g = tid >> 6, l64 = tid & 63;
    for (int cc = 0; cc < 8; cc++) {
        int c = c0 + cc;
        int base = g_offsets[c];
        int cnt  = g_offsets[c + 1] - base;
        float4 ov = ((const float4*)(TsPp + cc * 256))[l64];
        for (int i0 = 0; i0 < cnt; i0 += 256) {
            int m = min(256, cnt - i0);
            __syncthreads();
            if (tid < m) sids[tid] = g_sorted[base + i0 + tid];
            __syncthreads();
            for (int k = 0; k < m; k += 4) {
                int idx = k + g;
                if (idx < m) {
                    size_t n = (size_t)sids[idx];
                    ((float4*)out)[n * 64 + l64] = ov;
                }
            }
        }
    }
}

// ---------------- launch ----------------
extern "C" void kernel_launch(void* const* d_in, const int* in_sizes, int n_in,
                              void* d_out, int out_size) {
    const float* x  = (const float*)d_in[0];
    const int*   ca = (const int*)d_in[1];
    // d_in[2] = batch (unused)
    const float* Wk = (const float*)d_in[3];
    const float* bk = (const float*)d_in[4];
    const float* Wv = (const float*)d_in[5];
    const float* bv = (const float*)d_in[6];
    const float* Wo = (const float*)d_in[7];
    const float* bo = (const float*)d_in[8];
    const float* pq = (const float*)d_in[9];
    float* out = (float*)d_out;

    cudaFuncSetAttribute(k_main, cudaFuncAttributeMaxDynamicSharedMemorySize,
                         SMEM_MAIN);

    k_prep_hist<<<NB + 8, 256>>>(Wk, bk, pq, ca);
    k_scan2    <<<1, 1024>>>();
    k_scatter2 <<<NB, 256>>>(ca);
    k_main     <<<SPLIT * NC, 256, SMEM_MAIN>>>(x);
    k_fused    <<<NC / 8, 256>>>(Wv, bv, Wo, bo, out);
}